// round 17
// baseline (speedup 1.0000x reference)
#include <cuda_runtime.h>
#include <cuda_fp16.h>
#include <math_constants.h>
#include <math.h>
#include <cstdint>

// B=4, L=1024, D=1024, H=16, HD=64.
// S[q,k] = (q+rr)·x_k + (q+rw)·pos[k-q+L] == Â[q]·K̂[k], K=128 (angle addition).
// R17: flash overhead trim — register bitmask for mask, incremental cp.async
//      pointers (no per-tile 64-bit address rebuild). Arithmetic unchanged.

// ---------------------------------------------------------------------------
// Device scratch
// ---------------------------------------------------------------------------
__device__ __align__(16) __half g_xh[4096 * 1024];
__device__ __align__(16) __half g_xl[4096 * 1024];
__device__ __align__(16) __half g_wh[2048 * 1024];      // Wqv^T hi [n][k]
__device__ __align__(16) __half g_wl[2048 * 1024];
__device__ __align__(16) __half g_uh[4096 * 1024];      // u = q + rr, fp16 hi
__device__ __align__(16) __half g_ul[4096 * 1024];      // u lo
__device__ __align__(16) __half g_vth[64 * 64 * 1024];  // V^T fp16 [bh*64+d][tok]
__device__ __align__(16) float g_trig[1024 * 64];       // fp32 [p][i]=sin, [p][32+i]=cos
__device__ __align__(16) __half g_tgh[1024 * 64];       // fp16 hi of trig
__device__ __align__(16) __half g_tgl[1024 * 64];       // fp16 lo of trig

// ---------------------------------------------------------------------------
// helpers
// ---------------------------------------------------------------------------
__device__ __forceinline__ uint32_t smem_u32(const void* p) {
    uint32_t a;
    asm("{ .reg .u64 t; cvta.to.shared.u64 t, %1; cvt.u32.u64 %0, t; }" : "=r"(a) : "l"(p));
    return a;
}
__device__ __forceinline__ void mma_f16(float* c, const uint32_t* a, const uint32_t* b) {
    asm volatile(
        "mma.sync.aligned.m16n8k16.row.col.f32.f16.f16.f32 "
        "{%0,%1,%2,%3}, {%4,%5,%6,%7}, {%8,%9}, {%0,%1,%2,%3};"
        : "+f"(c[0]), "+f"(c[1]), "+f"(c[2]), "+f"(c[3])
        : "r"(a[0]), "r"(a[1]), "r"(a[2]), "r"(a[3]), "r"(b[0]), "r"(b[1]));
}
__device__ __forceinline__ void ldsm4(uint32_t* r, uint32_t addr) {
    asm volatile("ldmatrix.sync.aligned.m8n8.x4.shared.b16 {%0,%1,%2,%3}, [%4];"
        : "=r"(r[0]), "=r"(r[1]), "=r"(r[2]), "=r"(r[3]) : "r"(addr));
}
__device__ __forceinline__ uint32_t packh2(float e0, float e1) {
    __half2 h = __floats2half2_rn(e0, e1);
    return *(uint32_t*)&h;
}
#define CP16(saddr, gptr) \
    asm volatile("cp.async.ca.shared.global [%0], [%1], 16;" \
        :: "r"(saddr), "l"(__cvta_generic_to_global(gptr)))
#define CP_COMMIT() asm volatile("cp.async.commit_group;")
#define CP_WAIT(n)  asm volatile("cp.async.wait_group %0;" :: "n"(n))

// ---------------------------------------------------------------------------
// K0: trig tables (fp32 + fp16 hi/lo).
// ---------------------------------------------------------------------------
__global__ void k_trig() {
    int p = blockIdx.x, i = threadIdx.x;
    double f = exp(-(double)i * (log(10000.0) / 31.0));
    double ang = (double)p * f;
    float s = (float)sin(ang), c = (float)cos(ang);
    g_trig[p * 64 + i] = s;
    g_trig[p * 64 + 32 + i] = c;
    __half sh = __float2half_rn(s), ch = __float2half_rn(c);
    g_tgh[p * 64 + i] = sh;
    g_tgh[p * 64 + 32 + i] = ch;
    g_tgl[p * 64 + i] = __float2half_rn(s - __half2float(sh));
    g_tgl[p * 64 + 32 + i] = __float2half_rn(c - __half2float(ch));
}

// ---------------------------------------------------------------------------
// K1 (fused): x decomposition (blocks < 16384, coalesced) and W^T via smem
// tile transpose (blocks >= 16384).
// ---------------------------------------------------------------------------
__global__ __launch_bounds__(256) void k_decomp(const float* __restrict__ x,
                                                const float* __restrict__ W) {
    __shared__ float tile[64][65];
    int bid = blockIdx.x;
    if (bid < 16384) {
        int idx = bid * 256 + threadIdx.x;
        float f = x[idx];
        __half h = __float2half_rn(f);
        g_xh[idx] = h;
        g_xl[idx] = __float2half_rn(f - __half2float(h));
    } else {
        int wt = bid - 16384;                 // 0..511
        int k0 = (wt >> 5) * 64;
        int n0 = (wt & 31) * 64;
        int tid = threadIdx.x;
#pragma unroll
        for (int it = 0; it < 16; it++) {
            int idx = tid + it * 256;
            int r = idx >> 6, c = idx & 63;
            tile[r][c] = W[(size_t)(k0 + r) * 2048 + n0 + c];
        }
        __syncthreads();
#pragma unroll
        for (int it = 0; it < 16; it++) {
            int idx = tid + it * 256;
            int r = idx >> 6, c = idx & 63;
            float f = tile[c][r];
            __half h = __float2half_rn(f);
            size_t o = (size_t)(n0 + r) * 1024 + k0 + c;
            g_wh[o] = h;
            g_wl[o] = __float2half_rn(f - __half2float(h));
        }
    }
}

// ---------------------------------------------------------------------------
// K2: qv = x @ Wqv. q-half 3-product, v-half 1-product (xh·Wh).
// Epilogue: q -> uh/ul fp16 split; v -> g_vth fp16 TRANSPOSED (direct).
// ---------------------------------------------------------------------------
#define STAGE_BYTES 30720
#define QV_SMEM (2 * STAGE_BYTES)

__device__ __forceinline__ void stage_load(
    uint32_t sb, const __half* Ah, const __half* Al,
    const __half* Bh, const __half* Bl,
    size_t aRow, size_t bRow, int lda, int k0, int tid, bool lo)
{
#pragma unroll
    for (int it = 0; it < 2; it++) {
        int idx = tid + it * 256;
        int r = idx >> 2, c = idx & 3;
        uint32_t so = r * 80 + c * 16;
        size_t go = (aRow + r) * (size_t)lda + k0 + c * 8;
        CP16(sb + so, Ah + go);
        if (lo) CP16(sb + 10240 + so, Al + go);
    }
    {
        int r = tid >> 2, c = tid & 3;
        uint32_t so = r * 80 + c * 16;
        size_t go = (bRow + r) * (size_t)lda + k0 + c * 8;
        CP16(sb + 20480 + so, Bh + go);
        if (lo) CP16(sb + 25600 + so, Bl + go);
    }
}
__device__ __forceinline__ void stage_mma(uint32_t sb, int wm, int wn, int lane,
                                          float acc[2][4][4], bool three)
{
    int rsel = lane & 15;
    uint32_t csel = ((lane >> 4) << 3);
#pragma unroll
    for (int kc = 0; kc < 32; kc += 16) {
        uint32_t colB = (kc + csel) * 2;
        uint32_t ah[2][4], al[2][4], bhf[2][4], blf[2][4];
#pragma unroll
        for (int mi = 0; mi < 2; mi++) {
            uint32_t ad = sb + (uint32_t)((wm + mi * 16 + rsel) * 80) + colB;
            ldsm4(ah[mi], ad);
            if (three) ldsm4(al[mi], ad + 10240);
        }
#pragma unroll
        for (int p = 0; p < 2; p++) {
            uint32_t bd = sb + 20480 + (uint32_t)((wn + p * 16 + rsel) * 80) + colB;
            ldsm4(bhf[p], bd);
            if (three) ldsm4(blf[p], bd + 5120);
        }
#pragma unroll
        for (int mi = 0; mi < 2; mi++)
#pragma unroll
            for (int ni = 0; ni < 4; ni++) {
                int p = ni >> 1, o = ni & 1;
                uint32_t bq[2] = { bhf[p][o], bhf[p][o + 2] };
                mma_f16(acc[mi][ni], ah[mi], bq);
                if (three) {
                    uint32_t bql[2] = { blf[p][o], blf[p][o + 2] };
                    mma_f16(acc[mi][ni], ah[mi], bql);
                    mma_f16(acc[mi][ni], al[mi], bq);
                }
            }
    }
}

__global__ __launch_bounds__(256, 2) void k_qv_mma(const float* __restrict__ rr) {
    extern __shared__ char dynsmem[];
    uint32_t sbase = smem_u32(dynsmem);
    int tid = threadIdx.x, wid = tid >> 5, lane = tid & 31;
    int wm = (wid >> 1) * 32, wn = (wid & 1) * 32;
    int g = lane >> 2, t = lane & 3;
    int brow = blockIdx.y * 128, bcol = blockIdx.x * 64;
    bool is_q = (bcol < 1024);

    float acc[2][4][4] = {};
    const int NS = 32;
    stage_load(sbase, g_xh, g_xl, g_wh, g_wl, brow, bcol, 1024, 0, tid, is_q);
    CP_COMMIT();
    for (int s = 0; s < NS; s++) {
        CP_WAIT(0);
        __syncthreads();
        if (s + 1 < NS) {
            stage_load(sbase + ((s + 1) & 1) * STAGE_BYTES, g_xh, g_xl, g_wh, g_wl,
                       brow, bcol, 1024, (s + 1) * 32, tid, is_q);
            CP_COMMIT();
        }
        stage_mma(sbase + (s & 1) * STAGE_BYTES, wm, wn, lane, acc, is_q);
    }

#pragma unroll
    for (int mi = 0; mi < 2; mi++)
#pragma unroll
        for (int ni = 0; ni < 4; ni++) {
            int row0 = brow + wm + mi * 16 + g;
            int cn = bcol + wn + ni * 8 + 2 * t;
            float2 v0 = make_float2(acc[mi][ni][0], acc[mi][ni][1]);
            float2 v1 = make_float2(acc[mi][ni][2], acc[mi][ni][3]);
            if (is_q) {
                float2 rb = *(const float2*)(rr + cn);
                v0.x += rb.x; v0.y += rb.y;
                v1.x += rb.x; v1.y += rb.y;
                __half2 h0 = __floats2half2_rn(v0.x, v0.y);
                __half2 l0 = __floats2half2_rn(v0.x - __half2float(h0.x),
                                               v0.y - __half2float(h0.y));
                __half2 h1 = __floats2half2_rn(v1.x, v1.y);
                __half2 l1 = __floats2half2_rn(v1.x - __half2float(h1.x),
                                               v1.y - __half2float(h1.y));
                *(__half2*)&g_uh[(size_t)row0 * 1024 + cn] = h0;
                *(__half2*)&g_ul[(size_t)row0 * 1024 + cn] = l0;
                *(__half2*)&g_uh[(size_t)(row0 + 8) * 1024 + cn] = h1;
                *(__half2*)&g_ul[(size_t)(row0 + 8) * 1024 + cn] = l1;
            } else {
                int vc = cn - 1024;
                int h2 = vc >> 6, d = vc & 63;
                int b2 = row0 >> 10, tok = row0 & 1023;
                size_t base = ((size_t)((b2 << 4) + h2) * 64 + d) * 1024 + tok;
                g_vth[base]            = __float2half_rn(v0.x);
                g_vth[base + 1024]     = __float2half_rn(v0.y);
                g_vth[base + 8]        = __float2half_rn(v1.x);
                g_vth[base + 1024 + 8] = __float2half_rn(v1.y);
            }
        }
}

// ---------------------------------------------------------------------------
// K5: flash attention. In-CTA Â trig prologue; register bitmask; incremental
// cp.async pointers. Arithmetic identical to R16.
// ---------------------------------------------------------------------------
#define FA_ACH 10240
#define FA_ALO 40960
#define FA_KBASE 81920
#define FA_KCH 5120
#define FA_KLO 20480
#define FA_VOFF 40960
#define FA_STAGE 51200
#define FA_SMEM (FA_KBASE + 2 * FA_STAGE)   // 184320

__global__ __launch_bounds__(256, 1) void k_flash(const int* __restrict__ mask,
                                                  const float* __restrict__ rr,
                                                  const float* __restrict__ rw,
                                                  float* __restrict__ out) {
    extern __shared__ char dynsmem[];
    __shared__ int msk[1024];
    uint32_t sb = smem_u32(dynsmem);
    int bh = blockIdx.y, b = bh >> 4, h = bh & 15;
    int brow = blockIdx.x * 128;
    int tid = threadIdx.x, wid = tid >> 5, lane = tid & 31;
    int wm = wid * 16;
    int g = lane >> 2, t = lane & 3;
    int rsel = lane & 15;
    uint32_t csel = ((lane >> 4) << 3);

    // ---- incremental K/V load state (6 cp.async slots per thread) ----
    const __half* pK[4];
    const __half* pKl[4];
    uint32_t soK[4];
    uint32_t strK[4];
#pragma unroll
    for (int it = 0; it < 4; it++) {
        int idx = tid + it * 256;              // 0..1023 = 64 rows x 16 cc
        int r = idx >> 4, cc = idx & 15;
        soK[it] = (cc >> 2) * FA_KCH + r * 80 + (cc & 3) * 16;
        if (cc < 8) {
            size_t go = (size_t)(b * 1024 + r) * 1024 + h * 64
                      + (cc >> 2) * 32 + (cc & 3) * 8;
            pK[it] = g_xh + go; pKl[it] = g_xl + go;
            strK[it] = 64 * 1024;
        } else {
            size_t go = (size_t)r * 64 + ((cc >> 2) - 2) * 32 + (cc & 3) * 8;
            pK[it] = g_tgh + go; pKl[it] = g_tgl + go;
            strK[it] = 64 * 64;
        }
    }
    const __half* pV[2];
    uint32_t soV[2];
#pragma unroll
    for (int it = 0; it < 2; it++) {
        int idx = tid + it * 256;              // 0..511
        int r = idx >> 3, cc = idx & 7;
        int c = cc >> 2, c4 = cc & 3;
        soV[it] = c * FA_KCH + r * 80 + c4 * 16;
        pV[it] = g_vth + (size_t)(bh * 64 + r) * 1024 + c * 32 + c4 * 8;
    }

    // ---- Â content chunks 0-1 via cp.async ----
#pragma unroll
    for (int it = 0; it < 4; it++) {
        int idx = tid + it * 256;
        int r = idx >> 3, cc = idx & 7;
        uint32_t so = (cc >> 2) * FA_ACH + r * 80 + (cc & 3) * 16;
        size_t go = (size_t)(b * 1024 + brow + r) * 1024 + h * 64
                  + (cc >> 2) * 32 + (cc & 3) * 8;
        CP16(sb + so, g_uh + go);
        CP16(sb + FA_ALO + so, g_ul + go);
    }
    // ---- K/V stage 0 ----
    {
        uint32_t st = sb + FA_KBASE;
#pragma unroll
        for (int it = 0; it < 4; it++) {
            CP16(st + soK[it], pK[it]);
            CP16(st + FA_KLO + soK[it], pKl[it]);
            pK[it] += strK[it]; pKl[it] += strK[it];
        }
        uint32_t sv = st + FA_VOFF;
#pragma unroll
        for (int it = 0; it < 2; it++) {
            CP16(sv + soV[it], pV[it]);
            pV[it] += 64;
        }
    }
    CP_COMMIT();

    // ---- Â trig half computed in-CTA (identical math to build_A) ----
    {
        int i = lane;
        float rr0 = rr[h * 64 + i],      rw0 = rw[h * 64 + i];
        float rr1 = rr[h * 64 + 32 + i], rw1 = rw[h * 64 + 32 + i];
#pragma unroll
        for (int j = 0; j < 16; j++) {
            int r = wid * 16 + j;
            size_t uo = (size_t)(b * 1024 + brow + r) * 1024 + h * 64;
            float u0 = __half2float(g_uh[uo + i]) + __half2float(g_ul[uo + i]);
            float u1 = __half2float(g_uh[uo + 32 + i]) + __half2float(g_ul[uo + 32 + i]);
            float w0 = u0 - rr0 + rw0;
            float w1 = u1 - rr1 + rw1;
            const float* tg = g_trig + (size_t)(brow + r) * 64;
            float sq = tg[i], cq = tg[32 + i];
            float a1 = w0 * cq + w1 * sq;
            float a2 = w1 * cq - w0 * sq;
            __half hh1 = __float2half_rn(a1);
            __half hh2 = __float2half_rn(a2);
            uint32_t off = (uint32_t)(r * 80 + i * 2);
            *(__half*)(dynsmem + 2 * FA_ACH + off) = hh1;
            *(__half*)(dynsmem + FA_ALO + 2 * FA_ACH + off) =
                __float2half_rn(a1 - __half2float(hh1));
            *(__half*)(dynsmem + 3 * FA_ACH + off) = hh2;
            *(__half*)(dynsmem + FA_ALO + 3 * FA_ACH + off) =
                __float2half_rn(a2 - __half2float(hh2));
        }
    }
    for (int i = tid; i < 1024; i += 256) msk[i] = mask[b * 1024 + i];
    __syncthreads();

    // ---- pack the 256 mask bits this thread ever tests into 8 u32 ----
    uint32_t mb[8];
#pragma unroll
    for (int kt2 = 0; kt2 < 8; kt2++) {
        uint32_t w = 0;
#pragma unroll
        for (int half = 0; half < 2; half++) {
            int kb = (kt2 * 2 + half) * 64;
#pragma unroll
            for (int ni = 0; ni < 8; ni++) {
                int kc = kb + ni * 8 + 2 * t;
                if (msk[kc])     w |= 1u << (half * 16 + ni * 2);
                if (msk[kc + 1]) w |= 1u << (half * 16 + ni * 2 + 1);
            }
        }
        mb[kt2] = w;
    }

    float oacc[8][4] = {};
    float m0 = -CUDART_INF_F, m1 = -CUDART_INF_F, l0 = 0.0f, l1 = 0.0f;

    const int NT = 16;
    for (int kt = 0; kt < NT; kt++) {
        CP_WAIT(0);
        __syncthreads();
        if (kt + 1 < NT) {
            uint32_t st = sb + FA_KBASE + ((kt + 1) & 1) * FA_STAGE;
#pragma unroll
            for (int it = 0; it < 4; it++) {
                CP16(st + soK[it], pK[it]);
                CP16(st + FA_KLO + soK[it], pKl[it]);
                pK[it] += strK[it]; pKl[it] += strK[it];
            }
            uint32_t sv = st + FA_VOFF;
#pragma unroll
            for (int it = 0; it < 2; it++) {
                CP16(sv + soV[it], pV[it]);
                pV[it] += 64;
            }
            CP_COMMIT();
        }

        uint32_t Ks = sb + FA_KBASE + (kt & 1) * FA_STAGE;
        float sacc[8][4] = {};
#pragma unroll
        for (int ks = 0; ks < 8; ks++) {
            int c = ks >> 1;
            uint32_t colB = (((ks & 1) * 16) + csel) * 2;
            uint32_t ah[4], al[4], bhf[4][4], blf[4][4];
            uint32_t ad = sb + (uint32_t)(c * FA_ACH) + (uint32_t)((wm + rsel) * 80) + colB;
            ldsm4(ah, ad);
            ldsm4(al, ad + FA_ALO);
#pragma unroll
            for (int p = 0; p < 4; p++) {
                uint32_t kd = Ks + (uint32_t)(c * FA_KCH) + (uint32_t)((p * 16 + rsel) * 80) + colB;
                ldsm4(bhf[p], kd);
                ldsm4(blf[p], kd + FA_KLO);
            }
#pragma unroll
            for (int ni = 0; ni < 8; ni++) {
                int p = ni >> 1, o = ni & 1;
                uint32_t bq[2]  = { bhf[p][o], bhf[p][o + 2] };
                uint32_t bql[2] = { blf[p][o], blf[p][o + 2] };
                mma_f16(sacc[ni], ah, bq);
                mma_f16(sacc[ni], ah, bql);
                mma_f16(sacc[ni], al, bq);
            }
        }

        // ---- online softmax (mask via register bits) ----
        uint32_t wbits = mb[kt >> 1] >> ((kt & 1) << 4);
        float tmax0 = -CUDART_INF_F, tmax1 = -CUDART_INF_F;
#pragma unroll
        for (int ni = 0; ni < 8; ni++) {
            if (!((wbits >> (ni * 2)) & 1u))     { sacc[ni][0] = -CUDART_INF_F; sacc[ni][2] = -CUDART_INF_F; }
            if (!((wbits >> (ni * 2 + 1)) & 1u)) { sacc[ni][1] = -CUDART_INF_F; sacc[ni][3] = -CUDART_INF_F; }
            tmax0 = fmaxf(tmax0, fmaxf(sacc[ni][0], sacc[ni][1]));
            tmax1 = fmaxf(tmax1, fmaxf(sacc[ni][2], sacc[ni][3]));
        }
        tmax0 = fmaxf(tmax0, __shfl_xor_sync(0xffffffffu, tmax0, 1));
        tmax0 = fmaxf(tmax0, __shfl_xor_sync(0xffffffffu, tmax0, 2));
        tmax1 = fmaxf(tmax1, __shfl_xor_sync(0xffffffffu, tmax1, 1));
        tmax1 = fmaxf(tmax1, __shfl_xor_sync(0xffffffffu, tmax1, 2));
        float nm0 = fmaxf(m0, tmax0), nm1 = fmaxf(m1, tmax1);
        float sc0 = __expf(m0 - nm0), sc1 = __expf(m1 - nm1);
        m0 = nm0; m1 = nm1;

        float rs0 = 0.0f, rs1 = 0.0f;
        uint32_t aPh[4][4];
#pragma unroll
        for (int ni = 0; ni < 8; ni++) {
            float p0 = __expf(sacc[ni][0] - nm0);
            float p1 = __expf(sacc[ni][1] - nm0);
            float p2 = __expf(sacc[ni][2] - nm1);
            float p3 = __expf(sacc[ni][3] - nm1);
            rs0 += p0 + p1;
            rs1 += p2 + p3;
            int c2 = ni >> 1, o = ni & 1;
            aPh[c2][o * 2 + 0] = packh2(p0, p1);
            aPh[c2][o * 2 + 1] = packh2(p2, p3);
        }
        rs0 += __shfl_xor_sync(0xffffffffu, rs0, 1);
        rs0 += __shfl_xor_sync(0xffffffffu, rs0, 2);
        rs1 += __shfl_xor_sync(0xffffffffu, rs1, 1);
        rs1 += __shfl_xor_sync(0xffffffffu, rs1, 2);
        l0 = l0 * sc0 + rs0;
        l1 = l1 * sc1 + rs1;
#pragma unroll
        for (int ni2 = 0; ni2 < 8; ni2++) {
            oacc[ni2][0] *= sc0; oacc[ni2][1] *= sc0;
            oacc[ni2][2] *= sc1; oacc[ni2][3] *= sc1;
        }

        uint32_t Vs = Ks + FA_VOFF;
#pragma unroll
        for (int c2 = 0; c2 < 4; c2++) {
            int c = c2 >> 1;
            uint32_t colB = (((c2 & 1) * 16) + csel) * 2;
            uint32_t bvh[4][4];
#pragma unroll
            for (int p = 0; p < 4; p++) {
                uint32_t vd = Vs + (uint32_t)(c * FA_KCH) + (uint32_t)((p * 16 + rsel) * 80) + colB;
                ldsm4(bvh[p], vd);
            }
#pragma unroll
            for (int ni2 = 0; ni2 < 8; ni2++) {
                int p = ni2 >> 1, o = ni2 & 1;
                uint32_t bq[2] = { bvh[p][o], bvh[p][o + 2] };
                mma_f16(oacc[ni2], aPh[c2], bq);
            }
        }
    }

    float inv0 = 1.0f / l0, inv1 = 1.0f / l1;
    int row0 = b * 1024 + brow + wm + g;
    int row1 = row0 + 8;
#pragma unroll
    for (int ni2 = 0; ni2 < 8; ni2++) {
        int cn = h * 64 + ni2 * 8 + 2 * t;
        *(float2*)&out[(size_t)row0 * 1024 + cn] =
            make_float2(oacc[ni2][0] * inv0, oacc[ni2][1] * inv0);
        *(float2*)&out[(size_t)row1 * 1024 + cn] =
            make_float2(oacc[ni2][2] * inv1, oacc[ni2][3] * inv1);
    }
}

// ---------------------------------------------------------------------------
extern "C" void kernel_launch(void* const* d_in, const int* in_sizes, int n_in,
                              void* d_out, int out_size) {
    (void)in_sizes; (void)n_in; (void)out_size;
    const float* x    = (const float*)d_in[0];
    const float* Wqv  = (const float*)d_in[1];
    const float* rr   = (const float*)d_in[2];
    const float* rw   = (const float*)d_in[3];
    const int*   mask = (const int*)d_in[4];
    float* out = (float*)d_out;

    cudaFuncSetAttribute(k_qv_mma, cudaFuncAttributeMaxDynamicSharedMemorySize, QV_SMEM);
    cudaFuncSetAttribute(k_flash,  cudaFuncAttributeMaxDynamicSharedMemorySize, FA_SMEM);

    k_trig<<<1024, 32>>>();
    k_decomp<<<16384 + 512, 256>>>(x, Wqv);
    k_qv_mma<<<dim3(32, 32), 256, QV_SMEM>>>(rr);
    k_flash<<<dim3(8, 64), 256, FA_SMEM>>>(mask, rr, rw, out);
}